// round 2
// baseline (speedup 1.0000x reference)
#include <cuda_runtime.h>
#include <cuda_fp16.h>
#include <stdint.h>
#include <math.h>

// ---------------------------------------------------------------------------
// EncoderBlock: B=2, N=2048, E=1024, H=16, D=64, FF=4096, fp32 in/out.
// Strategy: fp16 tensor-core GEMMs (fp32 accum), fused flash attention,
// fused epilogues (bias/residual/GELU). All scratch in __device__ globals.
// ---------------------------------------------------------------------------

#define TOK    4096      // B*N tokens
#define EMB    1024
#define NHEAD  16
#define HDIM   64
#define FFDIM  4096
#define SEQ    2048
#define QKV3   3072
#define LNEPS  1e-5f
#define SM_SCALE 2.82842712474619f   // 64^0.25  (qk / sqrt(scale), scale=D^-0.5)

// ------------------------------- scratch -----------------------------------
__device__ __half g_xn   [(size_t)TOK * EMB];     // LN output (reused for LN1 and LN2)
__device__ __half g_qkv  [(size_t)TOK * QKV3];
__device__ __half g_wavg [(size_t)TOK * EMB];
__device__ float  g_x2   [(size_t)TOK * EMB];     // post-attention residual (fp32)
__device__ __half g_h    [(size_t)TOK * FFDIM];
__device__ __half g_cwqkv[(size_t)EMB * QKV3];
__device__ __half g_cwout[(size_t)EMB * EMB];
__device__ __half g_cw1  [(size_t)EMB * FFDIM];
__device__ __half g_cw2  [(size_t)FFDIM * EMB];

// ------------------------------- helpers -----------------------------------
__device__ __forceinline__ uint32_t smem_u32(const void* p) {
    return (uint32_t)__cvta_generic_to_shared(p);
}
__device__ __forceinline__ void ldsm_x4(uint32_t& r0, uint32_t& r1, uint32_t& r2, uint32_t& r3, uint32_t a) {
    asm volatile("ldmatrix.sync.aligned.m8n8.x4.shared.b16 {%0,%1,%2,%3},[%4];\n"
                 : "=r"(r0), "=r"(r1), "=r"(r2), "=r"(r3) : "r"(a));
}
__device__ __forceinline__ void ldsm_x4_t(uint32_t& r0, uint32_t& r1, uint32_t& r2, uint32_t& r3, uint32_t a) {
    asm volatile("ldmatrix.sync.aligned.m8n8.x4.trans.shared.b16 {%0,%1,%2,%3},[%4];\n"
                 : "=r"(r0), "=r"(r1), "=r"(r2), "=r"(r3) : "r"(a));
}
__device__ __forceinline__ void mma16816(float* c, const uint32_t* a, uint32_t b0, uint32_t b1) {
    asm volatile("mma.sync.aligned.m16n8k16.row.col.f32.f16.f16.f32 "
                 "{%0,%1,%2,%3},{%4,%5,%6,%7},{%8,%9},{%0,%1,%2,%3};\n"
                 : "+f"(c[0]), "+f"(c[1]), "+f"(c[2]), "+f"(c[3])
                 : "r"(a[0]), "r"(a[1]), "r"(a[2]), "r"(a[3]), "r"(b0), "r"(b1));
}
__device__ __forceinline__ void cp_async16(void* s, const void* g) {
    asm volatile("cp.async.cg.shared.global [%0], [%1], 16;\n" :: "r"(smem_u32(s)), "l"(g));
}
__device__ __forceinline__ void cp_commit() { asm volatile("cp.async.commit_group;\n"); }
__device__ __forceinline__ uint32_t f2h2(float a, float b) {
    __half2 h = __floats2half2_rn(a, b);
    return *(uint32_t*)&h;
}
__device__ __forceinline__ float gelu_exact(float x) {
    return 0.5f * x * (1.0f + erff(x * 0.70710678118654752f));
}

// -------------------------- weight fp32 -> fp16 -----------------------------
__global__ __launch_bounds__(256) void cvt_kernel(const float* __restrict__ s,
                                                  __half* __restrict__ d, int n4) {
    // n4 = n/4; vectorized float4 -> 2x half2
    for (int i = blockIdx.x * blockDim.x + threadIdx.x; i < n4; i += gridDim.x * blockDim.x) {
        float4 v = ((const float4*)s)[i];
        __half2* o = (__half2*)(d + (size_t)i * 4);
        o[0] = __floats2half2_rn(v.x, v.y);
        o[1] = __floats2half2_rn(v.z, v.w);
    }
}

// ----------------------------- LayerNorm ------------------------------------
// one block (256 thr) per row of 1024; fp32 stats, fp16 output
__global__ __launch_bounds__(256) void ln_kernel(const float* __restrict__ x,
                                                 const float* __restrict__ g,
                                                 const float* __restrict__ bb,
                                                 __half* __restrict__ out) {
    const int row = blockIdx.x;
    const int tid = threadIdx.x;
    const float4 v = ((const float4*)(x + (size_t)row * EMB))[tid];
    float s1 = v.x + v.y + v.z + v.w;
    float s2 = v.x * v.x + v.y * v.y + v.z * v.z + v.w * v.w;
    __shared__ float sh1[8], sh2[8], stats[2];
    #pragma unroll
    for (int o = 16; o; o >>= 1) {
        s1 += __shfl_xor_sync(0xffffffffu, s1, o);
        s2 += __shfl_xor_sync(0xffffffffu, s2, o);
    }
    if ((tid & 31) == 0) { sh1[tid >> 5] = s1; sh2[tid >> 5] = s2; }
    __syncthreads();
    if (tid == 0) {
        float S = 0.f, Q = 0.f;
        #pragma unroll
        for (int i = 0; i < 8; i++) { S += sh1[i]; Q += sh2[i]; }
        float mu = S * (1.0f / EMB);
        float var = Q * (1.0f / EMB) - mu * mu;
        stats[0] = mu;
        stats[1] = rsqrtf(var + LNEPS);
    }
    __syncthreads();
    const float mu = stats[0], rs = stats[1];
    const int c = tid * 4;
    const float4 gv = ((const float4*)g)[tid];
    const float4 bv = ((const float4*)bb)[tid];
    const float o0 = (v.x - mu) * rs * gv.x + bv.x;
    const float o1 = (v.y - mu) * rs * gv.y + bv.y;
    const float o2 = (v.z - mu) * rs * gv.z + bv.z;
    const float o3 = (v.w - mu) * rs * gv.w + bv.w;
    __half2* op = (__half2*)(out + (size_t)row * EMB + c);
    op[0] = __floats2half2_rn(o0, o1);
    op[1] = __floats2half2_rn(o2, o3);
}

// ------------------------------ GEMM ----------------------------------------
// C[M,N] = A[M,K] @ B[K,N], A/B fp16 row-major, fp32 accum.
// EPI 0: store half. EPI 1: half(gelu(acc+bias)). EPI 2: float(resid+acc+bias).
// BM=BN=128, BK=32, 256 threads, 2-stage cp.async pipeline.
template <int EPI>
__global__ __launch_bounds__(256) void gemm_kernel(const __half* __restrict__ A,
                                                   const __half* __restrict__ B,
                                                   const float* __restrict__ bias,
                                                   const float* __restrict__ resid,
                                                   void* __restrict__ Cout,
                                                   int M, int N, int K) {
    __shared__ __align__(16) __half sA[2][128][40];
    __shared__ __align__(16) __half sB[2][32][136];
    const int tid = threadIdx.x, lane = tid & 31, wid = tid >> 5;
    const int bm = blockIdx.y * 128, bn = blockIdx.x * 128;
    const int wm = (wid & 3) * 32, wn = (wid >> 2) * 64;

    float acc[2][8][4];
    #pragma unroll
    for (int mt = 0; mt < 2; mt++)
        #pragma unroll
        for (int nt = 0; nt < 8; nt++)
            #pragma unroll
            for (int i = 0; i < 4; i++) acc[mt][nt][i] = 0.f;

    const int KT = K >> 5;

    auto load_stage = [&](int st, int kt) {
        #pragma unroll
        for (int i = 0; i < 2; i++) {
            int idx = tid + i * 256;
            int ra = idx >> 2, ca = (idx & 3) * 8;
            cp_async16(&sA[st][ra][ca], A + (size_t)(bm + ra) * K + kt * 32 + ca);
            int rb = idx >> 4, cb = (idx & 15) * 8;
            cp_async16(&sB[st][rb][cb], B + (size_t)(kt * 32 + rb) * N + bn + cb);
        }
        cp_commit();
    };

    load_stage(0, 0);
    for (int kt = 0; kt < KT; kt++) {
        if (kt + 1 < KT) {
            load_stage((kt + 1) & 1, kt + 1);
            asm volatile("cp.async.wait_group 1;\n");
        } else {
            asm volatile("cp.async.wait_group 0;\n");
        }
        __syncthreads();
        const int st = kt & 1;
        #pragma unroll
        for (int ks = 0; ks < 2; ks++) {
            uint32_t af[2][4];
            #pragma unroll
            for (int mt = 0; mt < 2; mt++)
                ldsm_x4(af[mt][0], af[mt][1], af[mt][2], af[mt][3],
                        smem_u32(&sA[st][wm + mt * 16 + (lane & 15)][ks * 16 + (lane >> 4) * 8]));
            uint32_t bf[8][2];
            #pragma unroll
            for (int ntp = 0; ntp < 4; ntp++)
                ldsm_x4_t(bf[2 * ntp][0], bf[2 * ntp][1], bf[2 * ntp + 1][0], bf[2 * ntp + 1][1],
                          smem_u32(&sB[st][ks * 16 + (lane & 15)][wn + ntp * 16 + (lane >> 4) * 8]));
            #pragma unroll
            for (int mt = 0; mt < 2; mt++)
                #pragma unroll
                for (int nt = 0; nt < 8; nt++)
                    mma16816(acc[mt][nt], af[mt], bf[nt][0], bf[nt][1]);
        }
        __syncthreads();
    }

    // epilogue
    #pragma unroll
    for (int mt = 0; mt < 2; mt++) {
        const int r0 = bm + wm + mt * 16 + (lane >> 2);
        #pragma unroll
        for (int nt = 0; nt < 8; nt++) {
            const int c0 = bn + wn + nt * 8 + 2 * (lane & 3);
            float v0 = acc[mt][nt][0], v1 = acc[mt][nt][1];
            float v2 = acc[mt][nt][2], v3 = acc[mt][nt][3];
            if (EPI == 1 || EPI == 2) {
                const float bb0 = bias[c0], bb1 = bias[c0 + 1];
                v0 += bb0; v1 += bb1; v2 += bb0; v3 += bb1;
            }
            if (EPI == 1) {
                v0 = gelu_exact(v0); v1 = gelu_exact(v1);
                v2 = gelu_exact(v2); v3 = gelu_exact(v3);
            }
            const size_t i0 = (size_t)r0 * N + c0;
            const size_t i1 = (size_t)(r0 + 8) * N + c0;
            if (EPI == 2) {
                float* C = (float*)Cout;
                float2 o0 = make_float2(resid[i0] + v0, resid[i0 + 1] + v1);
                float2 o1 = make_float2(resid[i1] + v2, resid[i1 + 1] + v3);
                *(float2*)(C + i0) = o0;
                *(float2*)(C + i1) = o1;
            } else {
                __half* C = (__half*)Cout;
                *(__half2*)(C + i0) = __floats2half2_rn(v0, v1);
                *(__half2*)(C + i1) = __floats2half2_rn(v2, v3);
            }
        }
    }
}

// --------------------------- Flash attention --------------------------------
// grid: (SEQ/64, B*H), 128 threads. Each CTA: 64 q-rows of one (b,h).
// Q,K,V fp16 from g_qkv; online softmax fp32; output fp16 into g_wavg.
__global__ __launch_bounds__(128) void flash_kernel() {
    const int bh = blockIdx.y;
    const int b = bh >> 4, h = bh & 15;
    const int q0 = blockIdx.x * 64;
    const int tid = threadIdx.x, lane = tid & 31, wid = tid >> 5;

    __shared__ __align__(16) __half sQ[64][72];
    __shared__ __align__(16) __half sK[64][72];
    __shared__ __align__(16) __half sV[64][72];

    const __half* qbase = g_qkv + (size_t)(b * SEQ + q0) * QKV3 + h * HDIM;
    #pragma unroll
    for (int i = 0; i < 4; i++) {
        int idx = tid + 128 * i;          // 0..511
        int r = idx >> 3, c = (idx & 7) * 8;
        *(uint4*)&sQ[r][c] = *(const uint4*)(qbase + (size_t)r * QKV3 + c);
    }
    __syncthreads();

    uint32_t qf[4][4];
    {
        const int rr = wid * 16 + (lane & 15);
        const int cc = (lane >> 4) * 8;
        #pragma unroll
        for (int kk = 0; kk < 4; kk++)
            ldsm_x4(qf[kk][0], qf[kk][1], qf[kk][2], qf[kk][3],
                    smem_u32(&sQ[rr][kk * 16 + cc]));
    }

    float m_lo = -1e30f, m_hi = -1e30f, l_lo = 0.f, l_hi = 0.f;
    float O[8][4];
    #pragma unroll
    for (int nt = 0; nt < 8; nt++)
        #pragma unroll
        for (int i = 0; i < 4; i++) O[nt][i] = 0.f;

    const __half* kbase = g_qkv + (size_t)(b * SEQ) * QKV3 + EMB + h * HDIM;
    const __half* vbase = kbase + EMB;

    for (int kv0 = 0; kv0 < SEQ; kv0 += 64) {
        __syncthreads();   // all warps done with previous sK/sV
        #pragma unroll
        for (int i = 0; i < 4; i++) {
            int idx = tid + 128 * i;
            int r = idx >> 3, c = (idx & 7) * 8;
            size_t go = (size_t)(kv0 + r) * QKV3 + c;
            *(uint4*)&sK[r][c] = *(const uint4*)(kbase + go);
            *(uint4*)&sV[r][c] = *(const uint4*)(vbase + go);
        }
        __syncthreads();

        // S = Q @ K^T (per warp: 16 x 64)
        float S[8][4];
        #pragma unroll
        for (int nt = 0; nt < 8; nt++)
            #pragma unroll
            for (int i = 0; i < 4; i++) S[nt][i] = 0.f;
        #pragma unroll
        for (int kk = 0; kk < 4; kk++) {
            const int dcol = kk * 16 + ((lane >> 3) & 1) * 8;
            #pragma unroll
            for (int ntp = 0; ntp < 4; ntp++) {
                const int jrow = ntp * 16 + ((lane >> 4) << 3) + (lane & 7);
                uint32_t b0, b1, b2, b3;
                ldsm_x4(b0, b1, b2, b3, smem_u32(&sK[jrow][dcol]));
                mma16816(S[2 * ntp], qf[kk], b0, b1);
                mma16816(S[2 * ntp + 1], qf[kk], b2, b3);
            }
        }

        // online softmax (rows lane>>2 and lane>>2 + 8)
        float mx_lo = -1e30f, mx_hi = -1e30f;
        #pragma unroll
        for (int nt = 0; nt < 8; nt++) {
            S[nt][0] *= SM_SCALE; S[nt][1] *= SM_SCALE;
            S[nt][2] *= SM_SCALE; S[nt][3] *= SM_SCALE;
            mx_lo = fmaxf(mx_lo, fmaxf(S[nt][0], S[nt][1]));
            mx_hi = fmaxf(mx_hi, fmaxf(S[nt][2], S[nt][3]));
        }
        mx_lo = fmaxf(mx_lo, __shfl_xor_sync(0xffffffffu, mx_lo, 1));
        mx_lo = fmaxf(mx_lo, __shfl_xor_sync(0xffffffffu, mx_lo, 2));
        mx_hi = fmaxf(mx_hi, __shfl_xor_sync(0xffffffffu, mx_hi, 1));
        mx_hi = fmaxf(mx_hi, __shfl_xor_sync(0xffffffffu, mx_hi, 2));
        const float mn_lo = fmaxf(m_lo, mx_lo);
        const float mn_hi = fmaxf(m_hi, mx_hi);
        const float fac_lo = __expf(m_lo - mn_lo);
        const float fac_hi = __expf(m_hi - mn_hi);
        float sum_lo = 0.f, sum_hi = 0.f;
        #pragma unroll
        for (int nt = 0; nt < 8; nt++) {
            S[nt][0] = __expf(S[nt][0] - mn_lo);
            S[nt][1] = __expf(S[nt][1] - mn_lo);
            S[nt][2] = __expf(S[nt][2] - mn_hi);
            S[nt][3] = __expf(S[nt][3] - mn_hi);
            sum_lo += S[nt][0] + S[nt][1];
            sum_hi += S[nt][2] + S[nt][3];
        }
        sum_lo += __shfl_xor_sync(0xffffffffu, sum_lo, 1);
        sum_lo += __shfl_xor_sync(0xffffffffu, sum_lo, 2);
        sum_hi += __shfl_xor_sync(0xffffffffu, sum_hi, 1);
        sum_hi += __shfl_xor_sync(0xffffffffu, sum_hi, 2);
        l_lo = l_lo * fac_lo + sum_lo;
        l_hi = l_hi * fac_hi + sum_hi;
        #pragma unroll
        for (int nt = 0; nt < 8; nt++) {
            O[nt][0] *= fac_lo; O[nt][1] *= fac_lo;
            O[nt][2] *= fac_hi; O[nt][3] *= fac_hi;
        }
        m_lo = mn_lo; m_hi = mn_hi;

        // O += P @ V
        #pragma unroll
        for (int kj = 0; kj < 4; kj++) {
            uint32_t a[4];
            a[0] = f2h2(S[2 * kj][0],     S[2 * kj][1]);
            a[1] = f2h2(S[2 * kj][2],     S[2 * kj][3]);
            a[2] = f2h2(S[2 * kj + 1][0], S[2 * kj + 1][1]);
            a[3] = f2h2(S[2 * kj + 1][2], S[2 * kj + 1][3]);
            const int vrow = kj * 16 + (lane & 15);
            #pragma unroll
            for (int ntp = 0; ntp < 4; ntp++) {
                const int vcol = ntp * 16 + (lane >> 4) * 8;
                uint32_t b0, b1, b2, b3;
                ldsm_x4_t(b0, b1, b2, b3, smem_u32(&sV[vrow][vcol]));
                mma16816(O[2 * ntp],     a, b0, b1);
                mma16816(O[2 * ntp + 1], a, b2, b3);
            }
        }
    }

    // normalize + store
    const float inv_lo = 1.0f / l_lo;
    const float inv_hi = 1.0f / l_hi;
    const int r = q0 + wid * 16 + (lane >> 2);
    __half* outp = g_wavg + (size_t)(b * SEQ) * EMB + h * HDIM;
    #pragma unroll
    for (int nt = 0; nt < 8; nt++) {
        const int col = nt * 8 + 2 * (lane & 3);
        *(__half2*)(outp + (size_t)r * EMB + col) =
            __floats2half2_rn(O[nt][0] * inv_lo, O[nt][1] * inv_lo);
        *(__half2*)(outp + (size_t)(r + 8) * EMB + col) =
            __floats2half2_rn(O[nt][2] * inv_hi, O[nt][3] * inv_hi);
    }
}

// ------------------------------- launch -------------------------------------
extern "C" void kernel_launch(void* const* d_in, const int* in_sizes, int n_in,
                              void* d_out, int out_size) {
    const float* x     = (const float*)d_in[0];
    const float* w_qkv = (const float*)d_in[1];
    const float* w_out = (const float*)d_in[2];
    const float* b_out = (const float*)d_in[3];
    const float* ln1_g = (const float*)d_in[4];
    const float* ln1_b = (const float*)d_in[5];
    const float* ln2_g = (const float*)d_in[6];
    const float* ln2_b = (const float*)d_in[7];
    const float* w1    = (const float*)d_in[8];
    const float* b1    = (const float*)d_in[9];
    const float* w2    = (const float*)d_in[10];
    const float* b2    = (const float*)d_in[11];

    void *p_xn, *p_qkv, *p_wavg, *p_x2, *p_h, *p_cwqkv, *p_cwout, *p_cw1, *p_cw2;
    cudaGetSymbolAddress(&p_xn, g_xn);
    cudaGetSymbolAddress(&p_qkv, g_qkv);
    cudaGetSymbolAddress(&p_wavg, g_wavg);
    cudaGetSymbolAddress(&p_x2, g_x2);
    cudaGetSymbolAddress(&p_h, g_h);
    cudaGetSymbolAddress(&p_cwqkv, g_cwqkv);
    cudaGetSymbolAddress(&p_cwout, g_cwout);
    cudaGetSymbolAddress(&p_cw1, g_cw1);
    cudaGetSymbolAddress(&p_cw2, g_cw2);

    // weight conversion fp32 -> fp16 (vectorized; counts are /4)
    cvt_kernel<<<512, 256>>>(w_qkv, (__half*)p_cwqkv, EMB * QKV3 / 4);
    // LN1
    ln_kernel<<<TOK, 256>>>(x, ln1_g, ln1_b, (__half*)p_xn);
    cvt_kernel<<<512, 256>>>(w_out, (__half*)p_cwout, EMB * EMB / 4);
    cvt_kernel<<<512, 256>>>(w1,    (__half*)p_cw1,   EMB * FFDIM / 4);
    cvt_kernel<<<512, 256>>>(w2,    (__half*)p_cw2,   FFDIM * EMB / 4);

    // QKV projection: [4096,1024] @ [1024,3072] -> half
    gemm_kernel<0><<<dim3(QKV3 / 128, TOK / 128), 256>>>(
        (const __half*)p_xn, (const __half*)p_cwqkv, nullptr, nullptr, p_qkv, TOK, QKV3, EMB);
    // fused attention -> g_wavg (half)
    flash_kernel<<<dim3(SEQ / 64, 2 * NHEAD), 128>>>();
    // out projection + bias + residual(x) -> g_x2 (fp32)
    gemm_kernel<2><<<dim3(EMB / 128, TOK / 128), 256>>>(
        (const __half*)p_wavg, (const __half*)p_cwout, b_out, x, p_x2, TOK, EMB, EMB);
    // LN2
    ln_kernel<<<TOK, 256>>>((const float*)p_x2, ln2_g, ln2_b, (__half*)p_xn);
    // FF1 + bias + gelu -> g_h (half)
    gemm_kernel<1><<<dim3(FFDIM / 128, TOK / 128), 256>>>(
        (const __half*)p_xn, (const __half*)p_cw1, b1, nullptr, p_h, TOK, FFDIM, EMB);
    // FF2 + bias + residual(g_x2) -> d_out (fp32)
    gemm_kernel<2><<<dim3(EMB / 128, TOK / 128), 256>>>(
        (const __half*)p_h, (const __half*)p_cw2, b2, (const float*)p_x2, d_out, TOK, EMB, FFDIM);
}